// round 1
// baseline (speedup 1.0000x reference)
#include <cuda_runtime.h>

#define Fdim 64
#define Ldim 512
#define Bdim 256
#define NIDS 2000
#define TMAX 513   // counts range 0..512

// persistent device scratch (allocation-free rule: __device__ globals)
__device__ float g_M[3][Fdim * Fdim];   // w2@Wq, w2@Wk, w2@Wv
__device__ float g_cb[4][Fdim];         // b2, b2@Wq, b2@Wk, b2@Wv
__device__ float g_T[4][TMAX * Fdim];   // tables: feat,q,k,v (bias folded per lookup)

// ---------------------------------------------------------------------------
// Precompute combined projection matrices M_x = w2 @ Wx and bias vectors.
__global__ void build_M_kernel(const float* __restrict__ w2, const float* __restrict__ Wq,
                               const float* __restrict__ Wk, const float* __restrict__ Wv,
                               const float* __restrict__ b2)
{
    int t = threadIdx.x;
    for (int idx = t; idx < 3 * Fdim * Fdim; idx += blockDim.x) {
        int x = idx / (Fdim * Fdim);
        int r = idx - x * Fdim * Fdim;
        int f = r >> 6, g = r & 63;
        const float* W = (x == 0) ? Wq : ((x == 1) ? Wk : Wv);
        float acc = 0.f;
#pragma unroll 8
        for (int h = 0; h < Fdim; h++) acc += w2[f * Fdim + h] * W[h * Fdim + g];
        g_M[x][f * Fdim + g] = acc;
    }
    for (int idx = t; idx < 4 * Fdim; idx += blockDim.x) {
        int x = idx >> 6, g = idx & 63;
        if (x == 0) {
            g_cb[0][g] = b2[g];
        } else {
            const float* W = (x == 1) ? Wq : ((x == 2) ? Wk : Wv);
            float acc = 0.f;
            for (int h = 0; h < Fdim; h++) acc += b2[h] * W[h * Fdim + g];
            g_cb[x][g] = acc;
        }
    }
}

// Tables: T_x[c][g] = sum_f relu(c*w1[f]+b1[f]) * M_x[f][g] + cb_x[g]
// Two lookups (c0,c1) summed reproduce the reference encode exactly:
//   (relu(c0*w1+b1)+relu(c1*w1+b1)) @ w2 @ Wx + 2*b2@Wx
__global__ void build_T_kernel(const float* __restrict__ w1, const float* __restrict__ b1,
                               const float* __restrict__ w2)
{
    int c = blockIdx.x, x = blockIdx.y, g = threadIdx.x;
    __shared__ float r[Fdim];
    r[g] = fmaxf((float)c * w1[g] + b1[g], 0.f);
    __syncthreads();
    const float* M = (x == 0) ? w2 : g_M[x - 1];
    float acc = g_cb[x][g];
#pragma unroll 8
    for (int f = 0; f < Fdim; f++) acc += r[f] * M[f * Fdim + g];
    g_T[x][c * Fdim + g] = acc;
}

// ---------------------------------------------------------------------------
// Fused main kernel: one block per (direction, batch).
// Shared layout (floats unless noted):
//   k_sh   32768  : K matrix [512,64], becomes P=exp(K-max) in place
//   stage   4096  : V chunk staging [64,64]; later kg=1 accumulator dump
//   ctx_sh  4096  : ctx [64,64]
//   ctx2p   4096  : ctx@Wo in paired (f, f+32) float2 layout
//   hist    4000 ints : 2 histograms (self, other)
//   cnt     2048 ints : c0,c1,d0,d1 per token
//   part     512  : 8x64 partial column reductions
//   colmax    64, colinv 64
//   qbuf    1024  : per-warp softmaxed q rows
//   cvec     192  : bo, ln_g, ln_b
#define SMEM_BYTES 211840

__global__ void __launch_bounds__(512, 1) fused_kernel(
    const int* __restrict__ src, const int* __restrict__ dst,
    const float* __restrict__ Wo, const float* __restrict__ bo,
    const float* __restrict__ lng, const float* __restrict__ lnb,
    float* __restrict__ out)
{
    extern __shared__ char smraw[];
    float* k_sh   = (float*)smraw;
    float* stage  = k_sh + 32768;
    float* ctx_sh = stage + 4096;
    float* ctx2p  = ctx_sh + 4096;
    int*   hist   = (int*)(ctx2p + 4096);
    int*   cnt    = hist + 2 * NIDS;
    float* part   = (float*)(cnt + 4 * Ldim);
    float* colmax = part + 512;
    float* colinv = colmax + 64;
    float* qbuf   = colinv + 64;
    float* cvec   = qbuf + 1024;

    const int t = threadIdx.x;
    const int dir = blockIdx.x;
    const int b = blockIdx.y;
    const int* a_ids = (dir == 0 ? src : dst) + b * Ldim;
    const int* o_ids = (dir == 0 ? dst : src) + b * Ldim;

    // ---- histograms + counts ----
    for (int i = t; i < 2 * NIDS; i += 512) hist[i] = 0;
    if (t < 192) cvec[t] = (t < 64) ? bo[t] : ((t < 128) ? lng[t - 64] : lnb[t - 128]);
    __syncthreads();
    const int av = a_ids[t], ov = o_ids[t];
    atomicAdd(&hist[av], 1);
    atomicAdd(&hist[NIDS + ov], 1);
    __syncthreads();
    cnt[t]            = av ? hist[av]        : 0;   // c0: count of a in a
    cnt[Ldim + t]     = av ? hist[NIDS + av] : 0;   // c1: count of a in o
    cnt[2 * Ldim + t] = ov ? hist[NIDS + ov] : 0;   // d0: count of o in o
    cnt[3 * Ldim + t] = ov ? hist[ov]        : 0;   // d1: count of o in a
    __syncthreads();

    // ---- Phase A: K into smem, column softmax stats over L ----
    const float* Tk = g_T[2];
    {
        const int f = t & 63, grp = t >> 6;
        for (int l = grp; l < Ldim; l += 8) {
            int i0 = cnt[2 * Ldim + l], i1 = cnt[3 * Ldim + l];
            k_sh[l * 64 + f] = Tk[i0 * 64 + f] + Tk[i1 * 64 + f];
        }
    }
    __syncthreads();
    {
        const int f = t & 63, grp = t >> 6;
        float m = -3.4e38f;
        for (int l = grp; l < Ldim; l += 8) m = fmaxf(m, k_sh[l * 64 + f]);
        part[grp * 64 + f] = m;
    }
    __syncthreads();
    if (t < 64) {
        float m = part[t];
#pragma unroll
        for (int g = 1; g < 8; g++) m = fmaxf(m, part[g * 64 + t]);
        colmax[t] = m;
    }
    __syncthreads();
    {
        const int f = t & 63, grp = t >> 6;
        const float m = colmax[f];
        float s = 0.f;
        for (int l = grp; l < Ldim; l += 8) {
            float e = __expf(k_sh[l * 64 + f] - m);
            k_sh[l * 64 + f] = e;   // K -> P in place
            s += e;
        }
        part[grp * 64 + f] = s;
    }
    __syncthreads();
    if (t < 64) {
        float s = 0.f;
#pragma unroll
        for (int g = 0; g < 8; g++) s += part[g * 64 + t];
        colinv[t] = 1.0f / s;
    }
    __syncthreads();

    // ---- Phase B: ctx[d][e] = (sum_l P[l][d]*V[l][e]) * colinv[d] ----
    const float* Tv = g_T[3];
    {
        const int kg = t >> 8, tt = t & 255;
        const int dbase = (tt >> 4) << 2, ebase = (tt & 15) << 2;
        float a_[4][4] = {};
        for (int ch = 0; ch < 8; ch++) {
            {   // stage V rows [ch*64, ch*64+64)
                const int f = t & 63;
                const int lg = t >> 6;
#pragma unroll
                for (int rep = 0; rep < 8; rep++) {
                    int lloc = lg + rep * 8;
                    int l = ch * 64 + lloc;
                    int i0 = cnt[2 * Ldim + l], i1 = cnt[3 * Ldim + l];
                    stage[lloc * 64 + f] = Tv[i0 * 64 + f] + Tv[i1 * 64 + f];
                }
            }
            __syncthreads();
            for (int ll = kg; ll < 64; ll += 2) {
                int l = ch * 64 + ll;
                float4 p = *(const float4*)&k_sh[l * 64 + dbase];
                float4 v = *(const float4*)&stage[ll * 64 + ebase];
                float pv[4] = {p.x, p.y, p.z, p.w};
                float vv[4] = {v.x, v.y, v.z, v.w};
#pragma unroll
                for (int i = 0; i < 4; i++)
#pragma unroll
                    for (int j = 0; j < 4; j++) a_[i][j] += pv[i] * vv[j];
            }
            __syncthreads();
        }
        if (kg == 1) {
#pragma unroll
            for (int i = 0; i < 4; i++)
#pragma unroll
                for (int j = 0; j < 4; j++) stage[tt * 16 + i * 4 + j] = a_[i][j];
        }
        __syncthreads();
        if (kg == 0) {
#pragma unroll
            for (int i = 0; i < 4; i++) {
                float inv = colinv[dbase + i];
#pragma unroll
                for (int j = 0; j < 4; j++)
                    ctx_sh[(dbase + i) * 64 + ebase + j] =
                        (a_[i][j] + stage[tt * 16 + i * 4 + j]) * inv;
            }
        }
        __syncthreads();
    }

    // ---- ctx2 = ctx @ Wo, stored as float2 pairs (g, g+32) per d ----
    for (int idx = t; idx < 4096; idx += 512) {
        int d = idx >> 6, g = idx & 63;
        float a = 0.f;
#pragma unroll 8
        for (int e = 0; e < 64; e++) a += ctx_sh[d * 64 + e] * Wo[e * 64 + g];
        ctx2p[(d * 32 + (g & 31)) * 2 + (g >> 5)] = a;
    }
    __syncthreads();

    // ---- Phase C: per-token q softmax, attn = qs@ctx2, residual + LN ----
    const float* Tq = g_T[1];
    const float* Tf = g_T[0];
    {
        const int w = t >> 5, lane = t & 31;
        const float bo0 = cvec[lane], bo1 = cvec[32 + lane];
        const float g0 = cvec[64 + lane], g1 = cvec[96 + lane];
        const float be0 = cvec[128 + lane], be1 = cvec[160 + lane];
        for (int l = w; l < Ldim; l += 16) {
            int i0 = cnt[l], i1 = cnt[Ldim + l];
            float q0 = Tq[i0 * 64 + lane] + Tq[i1 * 64 + lane];
            float q1 = Tq[i0 * 64 + 32 + lane] + Tq[i1 * 64 + 32 + lane];
            float f0 = Tf[i0 * 64 + lane] + Tf[i1 * 64 + lane];
            float f1 = Tf[i0 * 64 + 32 + lane] + Tf[i1 * 64 + 32 + lane];
            // softmax over 64 features (one token per warp, 2 per lane)
            float m = fmaxf(q0, q1);
#pragma unroll
            for (int off = 16; off; off >>= 1) m = fmaxf(m, __shfl_xor_sync(0xffffffffu, m, off));
            float e0 = __expf(q0 - m), e1 = __expf(q1 - m);
            float s = e0 + e1;
#pragma unroll
            for (int off = 16; off; off >>= 1) s += __shfl_xor_sync(0xffffffffu, s, off);
            float coef = 0.125f / s;   // * F^-0.5
            __syncwarp();
            qbuf[w * 64 + lane] = e0 * coef;
            qbuf[w * 64 + 32 + lane] = e1 * coef;
            __syncwarp();
            float a0 = 0.f, a1 = 0.f;
#pragma unroll 16
            for (int d = 0; d < 64; d++) {
                float qd = qbuf[w * 64 + d];
                float2 cp = *(const float2*)&ctx2p[(d * 32 + lane) * 2];
                a0 += qd * cp.x;
                a1 += qd * cp.y;
            }
            float y0 = f0 + a0 + bo0;
            float y1 = f1 + a1 + bo1;
            float mu = y0 + y1;
#pragma unroll
            for (int off = 16; off; off >>= 1) mu += __shfl_xor_sync(0xffffffffu, mu, off);
            mu *= (1.0f / 64.0f);
            float dy0 = y0 - mu, dy1 = y1 - mu;
            float var = dy0 * dy0 + dy1 * dy1;
#pragma unroll
            for (int off = 16; off; off >>= 1) var += __shfl_xor_sync(0xffffffffu, var, off);
            var *= (1.0f / 64.0f);
            float rs = rsqrtf(var + 1e-5f);
            size_t o = (((size_t)dir * Bdim + b) * Ldim + l) * 64;
            out[o + lane]      = dy0 * rs * g0 + be0;
            out[o + 32 + lane] = dy1 * rs * g1 + be1;
        }
    }
}

// ---------------------------------------------------------------------------
extern "C" void kernel_launch(void* const* d_in, const int* in_sizes, int n_in,
                              void* d_out, int out_size)
{
    const int*   src = (const int*)d_in[0];
    const int*   dst = (const int*)d_in[1];
    const float* w1  = (const float*)d_in[2];
    const float* b1  = (const float*)d_in[3];
    const float* w2  = (const float*)d_in[4];
    const float* b2  = (const float*)d_in[5];
    const float* Wq  = (const float*)d_in[6];
    const float* Wk  = (const float*)d_in[7];
    const float* Wv  = (const float*)d_in[8];
    const float* Wo  = (const float*)d_in[9];
    const float* bo  = (const float*)d_in[10];
    const float* lng = (const float*)d_in[11];
    const float* lnb = (const float*)d_in[12];
    float* out = (float*)d_out;

    build_M_kernel<<<1, 256>>>(w2, Wq, Wk, Wv, b2);
    build_T_kernel<<<dim3(TMAX, 4), Fdim>>>(w1, b1, w2);

    cudaFuncSetAttribute(fused_kernel, cudaFuncAttributeMaxDynamicSharedMemorySize, SMEM_BYTES);
    fused_kernel<<<dim3(2, Bdim), 512, SMEM_BYTES>>>(src, dst, Wo, bo, lng, lnb, out);
}

// round 2
// speedup vs baseline: 7.1410x; 7.1410x over previous
#include <cuda_runtime.h>

#define Fdim 64
#define Ldim 512
#define Bdim 256
#define NIDS 2000
#define TMAX 513
#define HSZ  1024

// tables: 0=feat, 1=q, 2=k, 3=v   (token row = T[c0] + T[c1], biases folded)
__device__ float g_T[4][TMAX * Fdim];

// ---------------------------------------------------------------------------
// T_feat[c][g] = relu(c*w1+b1) @ w2 + b2
__global__ void build_Tfeat(const float* __restrict__ w1, const float* __restrict__ b1,
                            const float* __restrict__ w2, const float* __restrict__ b2)
{
    int c = blockIdx.x, g = threadIdx.x;
    __shared__ float r[Fdim];
    r[g] = fmaxf((float)c * w1[g] + b1[g], 0.f);
    __syncthreads();
    float acc = b2[g];
#pragma unroll 8
    for (int f = 0; f < Fdim; f++) acc += r[f] * w2[f * Fdim + g];
    g_T[0][c * Fdim + g] = acc;
}

// T_x[c] = T_feat[c] @ Wx   (x = q,k,v) — exact: (relu@w2+b2)@Wx
__global__ void build_Tproj(const float* __restrict__ Wq, const float* __restrict__ Wk,
                            const float* __restrict__ Wv)
{
    int c = blockIdx.x, x = blockIdx.y, g = threadIdx.x;
    __shared__ float r[Fdim];
    r[g] = g_T[0][c * Fdim + g];
    __syncthreads();
    const float* W = (x == 0) ? Wq : ((x == 1) ? Wk : Wv);
    float acc = 0.f;
#pragma unroll 8
    for (int f = 0; f < Fdim; f++) acc += r[f] * W[f * Fdim + g];
    g_T[1 + x][c * Fdim + g] = acc;
}

// ---------------------------------------------------------------------------
__device__ __forceinline__ int insert_pair(int key, int* hkey, volatile int* hslot,
                                           int* counter, int* keys)
{
    unsigned h = ((unsigned)key * 2654435761u) >> 22;  // 10-bit hash
    while (true) {
        int k = hkey[h];
        if (k == -1) k = atomicCAS(&hkey[h], -1, key);
        if (k == -1) {                       // we claimed this bucket
            int s = atomicAdd(counter, 1);
            keys[s] = key;
            __threadfence_block();
            hslot[h] = s;
            return s;
        }
        if (k == key) {                      // someone else owns it; wait for slot
            int s;
            while ((s = hslot[h]) < 0) { }
            return s;
        }
        h = (h + 1) & (HSZ - 1);
    }
}

// Shared-mem layout (ints then floats, 16B aligned boundaries)
//  ints  : hist[4000] | a_hkey[1024] a_hslot[1024] o_hkey[1024] o_hslot[1024]
//          a_keys[512] o_keys[512] o_mult[512] tok_aslot[512] counters[8]
//  floats: ctx[4096] Ebuf[4096] Vbuf[4096] colmax[64] colinv[64] part[256]
//          qbuf[512] cvec[192]
#define NINT (4000 + 4 * 1024 + 4 * 512 + 8)
#define SMEM_BYTES ((NINT + 3 * 4096 + 64 + 64 + 256 + 512 + 192) * 4)

__global__ void __launch_bounds__(256, 2) fused_kernel(
    const int* __restrict__ src, const int* __restrict__ dst,
    const float* __restrict__ Wo, const float* __restrict__ bo,
    const float* __restrict__ lng, const float* __restrict__ lnb,
    float* __restrict__ out)
{
    extern __shared__ char smraw[];
    int*   hist    = (int*)smraw;
    int*   a_hkey  = hist + 4000;
    int*   a_hslot = a_hkey + HSZ;
    int*   o_hkey  = a_hslot + HSZ;
    int*   o_hslot = o_hkey + HSZ;
    int*   a_keys  = o_hslot + HSZ;
    int*   o_keys  = a_keys + 512;
    int*   o_mult  = o_keys + 512;
    int*   tok_as  = o_mult + 512;
    int*   counters= tok_as + 512;
    float* ctx     = (float*)(hist + NINT);
    float* Ebuf    = ctx + 4096;
    float* Vbuf    = Ebuf + 4096;
    float* colmax  = Vbuf + 4096;
    float* colinv  = colmax + 64;
    float* part    = colinv + 64;
    float* qbuf    = part + 256;
    float* cvec    = qbuf + 512;

    const int t = threadIdx.x;
    const int dir = blockIdx.x;
    const int b = blockIdx.y;
    const int* a_ids = (dir == 0 ? src : dst) + b * Ldim;
    const int* o_ids = (dir == 0 ? dst : src) + b * Ldim;

    // ---- init ----
    for (int i = t; i < 4000; i += 256) hist[i] = 0;
    for (int i = t; i < 4 * HSZ; i += 256) a_hkey[i] = -1;   // hkey+hslot both -1
    for (int i = t; i < 512; i += 256) o_mult[i] = 0;
    if (t < 8) counters[t] = 0;
    if (t < 192) cvec[t] = (t < 64) ? bo[t] : ((t < 128) ? lng[t - 64] : lnb[t - 128]);
    __syncthreads();

    // ---- histograms ----
    const int av0 = a_ids[t], av1 = a_ids[t + 256];
    const int ov0 = o_ids[t], ov1 = o_ids[t + 256];
    atomicAdd(&hist[av0], 1);
    atomicAdd(&hist[av1], 1);
    atomicAdd(&hist[NIDS + ov0], 1);
    atomicAdd(&hist[NIDS + ov1], 1);
    __syncthreads();

    // ---- per-token count pairs -> dedupe via hash ----
#pragma unroll
    for (int rep = 0; rep < 2; rep++) {
        int l = t + rep * 256;
        int av = rep ? av1 : av0, ov = rep ? ov1 : ov0;
        int c0 = av ? hist[av] : 0, c1 = av ? hist[NIDS + av] : 0;
        tok_as[l] = insert_pair((c0 << 10) | c1, a_hkey, a_hslot, &counters[0], a_keys);
        int d0 = ov ? hist[NIDS + ov] : 0, d1 = ov ? hist[ov] : 0;
        int s = insert_pair((d0 << 10) | d1, o_hkey, o_hslot, &counters[1], o_keys);
        atomicAdd(&o_mult[s], 1);
    }
    __syncthreads();
    const int n_ap = counters[0], n_op = counters[1];

    // ---- column max of K over unique o-pairs ----
    const float* Tk = g_T[2];
    {
        const int d = t & 63, grp = t >> 6;
        float m = -3.4e38f;
        for (int p = grp; p < n_op; p += 4) {
            int key = o_keys[p], i0 = key >> 10, i1 = key & 1023;
            m = fmaxf(m, Tk[i0 * 64 + d] + Tk[i1 * 64 + d]);
        }
        part[grp * 64 + d] = m;
    }
    __syncthreads();
    if (t < 64) {
        float m = part[t];
#pragma unroll
        for (int g = 1; g < 4; g++) m = fmaxf(m, part[g * 64 + t]);
        colmax[t] = m;
    }
    __syncthreads();

    // ---- column sum (weighted by multiplicity) ----
    {
        const int d = t & 63, grp = t >> 6;
        float s = 0.f;
        const float cm = colmax[d];
        for (int p = grp; p < n_op; p += 4) {
            int key = o_keys[p], i0 = key >> 10, i1 = key & 1023;
            s += (float)o_mult[p] * __expf(Tk[i0 * 64 + d] + Tk[i1 * 64 + d] - cm);
        }
        part[grp * 64 + d] = s;
    }
    __syncthreads();
    if (t < 64) {
        float s = part[t];
#pragma unroll
        for (int g = 1; g < 4; g++) s += part[g * 64 + t];
        colinv[t] = 1.0f / s;
    }
    __syncthreads();

    // ---- ctx[d][e] = (sum_p E[p][d] * V[p][e]) * colinv[d], chunks of 64 pairs ----
    const float* Tv = g_T[3];
    {
        const int dbase = (t >> 4) << 2, ebase = (t & 15) << 2;
        float acc[4][4] = {};
        for (int pc = 0; pc < n_op; pc += 64) {
            const int cn = min(64, n_op - pc);
            for (int idx = t; idx < cn * 64; idx += 256) {
                int p = idx >> 6, d = idx & 63;
                int key = o_keys[pc + p], i0 = key >> 10, i1 = key & 1023;
                Ebuf[p * 64 + d] = (float)o_mult[pc + p] *
                    __expf(Tk[i0 * 64 + d] + Tk[i1 * 64 + d] - colmax[d]);
            }
            for (int idx = t; idx < cn * 64; idx += 256) {
                int p = idx >> 6, e = idx & 63;
                int key = o_keys[pc + p], i0 = key >> 10, i1 = key & 1023;
                Vbuf[p * 64 + e] = Tv[i0 * 64 + e] + Tv[i1 * 64 + e];
            }
            __syncthreads();
            for (int p = 0; p < cn; p++) {
                float4 ev = *(const float4*)&Ebuf[p * 64 + dbase];
                float4 vv = *(const float4*)&Vbuf[p * 64 + ebase];
                float e_[4] = {ev.x, ev.y, ev.z, ev.w};
                float v_[4] = {vv.x, vv.y, vv.z, vv.w};
#pragma unroll
                for (int i = 0; i < 4; i++)
#pragma unroll
                    for (int j = 0; j < 4; j++) acc[i][j] += e_[i] * v_[j];
            }
            __syncthreads();
        }
#pragma unroll
        for (int i = 0; i < 4; i++) {
            float inv = colinv[dbase + i];
#pragma unroll
            for (int j = 0; j < 4; j++)
                ctx[(dbase + i) * 64 + ebase + j] = acc[i][j] * inv;
        }
    }
    __syncthreads();

    // ---- ctx2 = ctx @ Wo, paired (g, g+32) layout into Ebuf ----
    for (int idx = t; idx < 4096; idx += 256) {
        int d = idx >> 6, g = idx & 63;
        float a = 0.f;
#pragma unroll 8
        for (int e = 0; e < 64; e++) a += ctx[d * 64 + e] * Wo[e * 64 + g];
        Ebuf[(d * 32 + (g & 31)) * 2 + (g >> 5)] = a;
    }
    __syncthreads();

    // ---- per unique a-pair: q softmax -> attn -> +feat -> LN; scatter to tokens ----
    const float* Tq = g_T[1];
    const float* Tf = g_T[0];
    {
        const int w = t >> 5, lane = t & 31;
        const float bo0 = cvec[lane], bo1 = cvec[32 + lane];
        const float g0 = cvec[64 + lane], g1 = cvec[96 + lane];
        const float be0 = cvec[128 + lane], be1 = cvec[160 + lane];
        const size_t outbase = (((size_t)dir * Bdim + b) * Ldim) * 64;

        for (int ac = 0; ac < n_ap; ac += 64) {
            const int an = min(64, n_ap - ac);
            for (int p = w; p < an; p += 8) {
                int key = a_keys[ac + p], i0 = key >> 10, i1 = key & 1023;
                float q0 = Tq[i0 * 64 + lane] + Tq[i1 * 64 + lane];
                float q1 = Tq[i0 * 64 + 32 + lane] + Tq[i1 * 64 + 32 + lane];
                float f0 = Tf[i0 * 64 + lane] + Tf[i1 * 64 + lane];
                float f1 = Tf[i0 * 64 + 32 + lane] + Tf[i1 * 64 + 32 + lane];
                float m = fmaxf(q0, q1);
#pragma unroll
                for (int off = 16; off; off >>= 1) m = fmaxf(m, __shfl_xor_sync(~0u, m, off));
                float e0 = __expf(q0 - m), e1 = __expf(q1 - m);
                float s = e0 + e1;
#pragma unroll
                for (int off = 16; off; off >>= 1) s += __shfl_xor_sync(~0u, s, off);
                float coef = 0.125f / s;   // F^-0.5 / sum
                qbuf[w * 64 + lane] = e0 * coef;
                qbuf[w * 64 + 32 + lane] = e1 * coef;
                __syncwarp();
                float a0 = 0.f, a1 = 0.f;
#pragma unroll 16
                for (int d = 0; d < 64; d++) {
                    float qd = qbuf[w * 64 + d];
                    float2 cp = *(const float2*)&Ebuf[(d * 32 + lane) * 2];
                    a0 += qd * cp.x;
                    a1 += qd * cp.y;
                }
                float y0 = f0 + a0 + bo0;
                float y1 = f1 + a1 + bo1;
                float mu = y0 + y1;
#pragma unroll
                for (int off = 16; off; off >>= 1) mu += __shfl_xor_sync(~0u, mu, off);
                mu *= (1.0f / 64.0f);
                float dy0 = y0 - mu, dy1 = y1 - mu;
                float var = dy0 * dy0 + dy1 * dy1;
#pragma unroll
                for (int off = 16; off; off >>= 1) var += __shfl_xor_sync(~0u, var, off);
                var *= (1.0f / 64.0f);
                float rs = rsqrtf(var + 1e-5f);
                Vbuf[p * 64 + lane]      = dy0 * rs * g0 + be0;
                Vbuf[p * 64 + 32 + lane] = dy1 * rs * g1 + be1;
                __syncwarp();
            }
            __syncthreads();
            // scatter: every token whose a-pair slot is in this chunk
            for (int l = w; l < Ldim; l += 8) {
                int s = tok_as[l] - ac;
                if ((unsigned)s < (unsigned)an && lane < 16) {
                    float4 v = *(const float4*)&Vbuf[s * 64 + lane * 4];
                    *(float4*)&out[outbase + (size_t)l * 64 + lane * 4] = v;
                }
            }
            __syncthreads();
        }
    }
}

// ---------------------------------------------------------------------------
extern "C" void kernel_launch(void* const* d_in, const int* in_sizes, int n_in,
                              void* d_out, int out_size)
{
    const int*   src = (const int*)d_in[0];
    const int*   dst = (const int*)d_in[1];
    const float* w1  = (const float*)d_in[2];
    const float* b1  = (const float*)d_in[3];
    const float* w2  = (const float*)d_in[4];
    const float* b2  = (const float*)d_in[5];
    const float* Wq  = (const float*)d_in[6];
    const float* Wk  = (const float*)d_in[7];
    const float* Wv  = (const float*)d_in[8];
    const float* Wo  = (const float*)d_in[9];
    const float* bo  = (const float*)d_in[10];
    const float* lng = (const float*)d_in[11];
    const float* lnb = (const float*)d_in[12];
    float* out = (float*)d_out;

    build_Tfeat<<<TMAX, Fdim>>>(w1, b1, w2, b2);
    build_Tproj<<<dim3(TMAX, 3), Fdim>>>(Wq, Wk, Wv);

    cudaFuncSetAttribute(fused_kernel, cudaFuncAttributeMaxDynamicSharedMemorySize, SMEM_BYTES);
    fused_kernel<<<dim3(2, Bdim), 256, SMEM_BYTES>>>(src, dst, Wo, bo, lng, lnb, out);
}

// round 3
// speedup vs baseline: 7.3979x; 1.0360x over previous
#include <cuda_runtime.h>

#define Fdim 64
#define Ldim 512
#define Bdim 256
#define NIDS 2000
#define TMAX 513
#define HSZ  512

// tables: 0=feat, 1=q, 2=k, 3=v   (token row = T[c0] + T[c1], biases folded)
__device__ float g_T[4][TMAX * Fdim];

// ---------------------------------------------------------------------------
// One launch builds all 4 tables. Block c: relu -> feat -> q/k/v.
__global__ void build_tables(const float* __restrict__ w1, const float* __restrict__ b1,
                             const float* __restrict__ w2, const float* __restrict__ b2,
                             const float* __restrict__ Wq, const float* __restrict__ Wk,
                             const float* __restrict__ Wv)
{
    const int c = blockIdx.x, t = threadIdx.x;
    __shared__ float r[Fdim];
    __shared__ float feat[Fdim];
    if (t < Fdim) r[t] = fmaxf((float)c * w1[t] + b1[t], 0.f);
    __syncthreads();
    if (t < Fdim) {
        float acc = b2[t];
#pragma unroll 8
        for (int f = 0; f < Fdim; f++) acc += r[f] * w2[f * Fdim + t];
        feat[t] = acc;
        g_T[0][c * Fdim + t] = acc;
    }
    __syncthreads();
    const int x = t >> 6, g = t & 63;
    if (x >= 1) {
        const float* W = (x == 1) ? Wq : ((x == 2) ? Wk : Wv);
        float acc = 0.f;
#pragma unroll 8
        for (int f = 0; f < Fdim; f++) acc += feat[f] * W[f * Fdim + g];
        g_T[x][c * Fdim + g] = acc;
    }
}

// ---------------------------------------------------------------------------
// Packed hash entry: (key << 10) | slot.  EMPTY = -1, PENDING slot = 0x3FF.
__device__ __forceinline__ int insert_pair(int key, int* tab, int* counter, int* keys)
{
    unsigned h = ((unsigned)key * 2654435761u) >> 23;   // 9-bit hash
    const int PEND = (key << 10) | 0x3FF;
    while (true) {
        int e = tab[h];
        if (e == -1) e = atomicCAS(&tab[h], -1, PEND);
        if (e == -1) {                    // we claimed this bucket
            int s = atomicAdd(counter, 1);
            keys[s] = key;
            __threadfence_block();
            atomicExch(&tab[h], (key << 10) | s);
            return s;
        }
        if ((e >> 10) == key) {           // wait for owner to publish slot
            int s = e & 0x3FF;
            while (s == 0x3FF) s = ((volatile int*)tab)[h] & 0x3FF;
            return s;
        }
        h = (h + 1) & (HSZ - 1);
    }
}

// Shared memory plan (ints, then floats; 56,416 B total -> 4 blocks/SM):
//  hist[2000] (a-count low16 | o-count high16), hashA[512], hashO[512],
//  a_keys[512], o_keys[512], o_mult[512], counters[8], tok_as ushort[512]
//  ctx[4096] | Ebuf[2048] Vbuf[2048] | colmax[64] colinv[64] part[256]
//  qbuf[512] cvec[192]
//  aliases: ctx2p = Ebuf(4096 spanning E+V), outrows = ctx
#define NINT (2000 + 2 * HSZ + 3 * 512 + 8 + 256)
#define NFLT (4096 + 2048 + 2048 + 64 + 64 + 256 + 512 + 192)
#define SMEM_BYTES ((NINT + NFLT) * 4)

__global__ void __launch_bounds__(256, 4) fused_kernel(
    const int* __restrict__ src, const int* __restrict__ dst,
    const float* __restrict__ Wo, const float* __restrict__ bo,
    const float* __restrict__ lng, const float* __restrict__ lnb,
    float* __restrict__ out)
{
    extern __shared__ int sm[];
    int* hist     = sm;
    int* hashA    = hist + 2000;
    int* hashO    = hashA + HSZ;
    int* a_keys   = hashO + HSZ;
    int* o_keys   = a_keys + 512;
    int* o_mult   = o_keys + 512;
    int* counters = o_mult + 512;
    unsigned short* tok_as = (unsigned short*)(counters + 8);
    float* ctx    = (float*)(counters + 8 + 256);
    float* Ebuf   = ctx + 4096;
    float* Vbuf   = Ebuf + 2048;
    float* colmax = Vbuf + 2048;
    float* colinv = colmax + 64;
    float* part   = colinv + 64;
    float* qbuf   = part + 256;
    float* cvec   = qbuf + 512;
    float* ctx2p   = Ebuf;   // 4096 (spans Ebuf+Vbuf)
    float* outrows = ctx;    // 4096

    const int t = threadIdx.x;
    const int dir = blockIdx.x;
    const int b = blockIdx.y;
    const int* a_ids = (dir == 0 ? src : dst) + b * Ldim;
    const int* o_ids = (dir == 0 ? dst : src) + b * Ldim;

    // ---- init ----
    for (int i = t; i < 2000; i += 256) hist[i] = 0;
    for (int i = t; i < 2 * HSZ; i += 256) hashA[i] = -1;
    for (int i = t; i < 512; i += 256) o_mult[i] = 0;
    if (t < 8) counters[t] = 0;
    if (t < 192) cvec[t] = (t < 64) ? bo[t] : ((t < 128) ? lng[t - 64] : lnb[t - 128]);
    __syncthreads();

    // ---- packed histograms: a-count in low 16, o-count in high 16 ----
    const int av0 = a_ids[t], av1 = a_ids[t + 256];
    const int ov0 = o_ids[t], ov1 = o_ids[t + 256];
    atomicAdd(&hist[av0], 1);
    atomicAdd(&hist[av1], 1);
    atomicAdd(&hist[ov0], 1 << 16);
    atomicAdd(&hist[ov1], 1 << 16);
    __syncthreads();

    // ---- per-token count pairs -> dedupe ----
#pragma unroll
    for (int rep = 0; rep < 2; rep++) {
        const int l = t + rep * 256;
        const int av = rep ? av1 : av0, ov = rep ? ov1 : ov0;
        int ha = hist[av];
        int akey = av ? (((ha & 0xFFFF) << 10) | (ha >> 16)) : 0;
        tok_as[l] = (unsigned short)insert_pair(akey, hashA, &counters[0], a_keys);
        int ho = hist[ov];
        int okey = ov ? (((ho >> 16) << 10) | (ho & 0xFFFF)) : 0;
        int s = insert_pair(okey, hashO, &counters[1], o_keys);
        atomicAdd(&o_mult[s], 1);
    }
    __syncthreads();
    const int n_ap = counters[0], n_op = counters[1];

    // ---- column max of K over unique o-pairs ----
    const float* Tk = g_T[2];
    {
        const int d = t & 63, grp = t >> 6;
        float m = -3.4e38f;
        for (int p = grp; p < n_op; p += 4) {
            int key = o_keys[p], i0 = key >> 10, i1 = key & 1023;
            m = fmaxf(m, Tk[i0 * 64 + d] + Tk[i1 * 64 + d]);
        }
        part[grp * 64 + d] = m;
    }
    __syncthreads();
    if (t < 64) {
        float m = part[t];
#pragma unroll
        for (int g = 1; g < 4; g++) m = fmaxf(m, part[g * 64 + t]);
        colmax[t] = m;
    }
    __syncthreads();

    // ---- weighted column sum ----
    {
        const int d = t & 63, grp = t >> 6;
        float s = 0.f;
        const float cm = colmax[d];
        for (int p = grp; p < n_op; p += 4) {
            int key = o_keys[p], i0 = key >> 10, i1 = key & 1023;
            s += (float)o_mult[p] * __expf(Tk[i0 * 64 + d] + Tk[i1 * 64 + d] - cm);
        }
        part[grp * 64 + d] = s;
    }
    __syncthreads();
    if (t < 64) {
        float s = part[t];
#pragma unroll
        for (int g = 1; g < 4; g++) s += part[g * 64 + t];
        colinv[t] = 1.0f / s;
    }
    __syncthreads();

    // ---- ctx[d][e] = (sum_p E[p][d]*V[p][e]) * colinv[d], 32-pair chunks ----
    const float* Tv = g_T[3];
    {
        const int dbase = (t >> 4) << 2, ebase = (t & 15) << 2;
        float acc[4][4] = {};
        for (int pc = 0; pc < n_op; pc += 32) {
            const int cn = min(32, n_op - pc);
            for (int idx = t; idx < cn * 64; idx += 256) {
                int p = idx >> 6, d = idx & 63;
                int key = o_keys[pc + p], i0 = key >> 10, i1 = key & 1023;
                Ebuf[p * 64 + d] = (float)o_mult[pc + p] *
                    __expf(Tk[i0 * 64 + d] + Tk[i1 * 64 + d] - colmax[d]);
            }
            for (int idx = t; idx < cn * 64; idx += 256) {
                int p = idx >> 6, e = idx & 63;
                int key = o_keys[pc + p], i0 = key >> 10, i1 = key & 1023;
                Vbuf[p * 64 + e] = Tv[i0 * 64 + e] + Tv[i1 * 64 + e];
            }
            __syncthreads();
            for (int p = 0; p < cn; p++) {
                float4 ev = *(const float4*)&Ebuf[p * 64 + dbase];
                float4 vv = *(const float4*)&Vbuf[p * 64 + ebase];
                float e_[4] = {ev.x, ev.y, ev.z, ev.w};
                float v_[4] = {vv.x, vv.y, vv.z, vv.w};
#pragma unroll
                for (int i = 0; i < 4; i++)
#pragma unroll
                    for (int j = 0; j < 4; j++) acc[i][j] += e_[i] * v_[j];
            }
            __syncthreads();
        }
#pragma unroll
        for (int i = 0; i < 4; i++) {
            float inv = colinv[dbase + i];
#pragma unroll
            for (int j = 0; j < 4; j++)
                ctx[(dbase + i) * 64 + ebase + j] = acc[i][j] * inv;
        }
    }
    __syncthreads();

    // ---- ctx2 = ctx @ Wo, paired (g, g+32) layout (aliases E/V bufs) ----
    for (int idx = t; idx < 4096; idx += 256) {
        int d = idx >> 6, g = idx & 63;
        float a = 0.f;
#pragma unroll 8
        for (int e = 0; e < 64; e++) a += ctx[d * 64 + e] * Wo[e * 64 + g];
        ctx2p[(d * 32 + (g & 31)) * 2 + (g >> 5)] = a;
    }
    __syncthreads();

    // ---- per unique a-pair: q softmax -> attn -> +feat -> LN; scatter ----
    const float* Tq = g_T[1];
    const float* Tf = g_T[0];
    {
        const int w = t >> 5, lane = t & 31;
        const float bo0 = cvec[lane], bo1 = cvec[32 + lane];
        const float g0 = cvec[64 + lane], g1 = cvec[96 + lane];
        const float be0 = cvec[128 + lane], be1 = cvec[160 + lane];
        const size_t outbase = (((size_t)dir * Bdim + b) * Ldim) * 64;

        for (int ac = 0; ac < n_ap; ac += 64) {
            const int an = min(64, n_ap - ac);
            for (int p = w; p < an; p += 8) {
                int key = a_keys[ac + p], i0 = key >> 10, i1 = key & 1023;
                float q0 = Tq[i0 * 64 + lane] + Tq[i1 * 64 + lane];
                float q1 = Tq[i0 * 64 + 32 + lane] + Tq[i1 * 64 + 32 + lane];
                float f0 = Tf[i0 * 64 + lane] + Tf[i1 * 64 + lane];
                float f1 = Tf[i0 * 64 + 32 + lane] + Tf[i1 * 64 + 32 + lane];
                float m = fmaxf(q0, q1);
#pragma unroll
                for (int off = 16; off; off >>= 1) m = fmaxf(m, __shfl_xor_sync(~0u, m, off));
                float e0 = __expf(q0 - m), e1 = __expf(q1 - m);
                float s = e0 + e1;
#pragma unroll
                for (int off = 16; off; off >>= 1) s += __shfl_xor_sync(~0u, s, off);
                float coef = 0.125f / s;        // F^-0.5 / sum
                qbuf[w * 64 + lane] = e0 * coef;
                qbuf[w * 64 + 32 + lane] = e1 * coef;
                __syncwarp();
                float a0 = 0.f, a1 = 0.f;
#pragma unroll 16
                for (int d = 0; d < 64; d++) {
                    float qd = qbuf[w * 64 + d];
                    float2 cp = *(const float2*)&ctx2p[(d * 32 + lane) * 2];
                    a0 += qd * cp.x;
                    a1 += qd * cp.y;
                }
                float y0 = f0 + a0 + bo0;
                float y1 = f1 + a1 + bo1;
                float mu = y0 + y1;
#pragma unroll
                for (int off = 16; off; off >>= 1) mu += __shfl_xor_sync(~0u, mu, off);
                mu *= (1.0f / 64.0f);
                float dy0 = y0 - mu, dy1 = y1 - mu;
                float var = dy0 * dy0 + dy1 * dy1;
#pragma unroll
                for (int off = 16; off; off >>= 1) var += __shfl_xor_sync(~0u, var, off);
                var *= (1.0f / 64.0f);
                float rs = rsqrtf(var + 1e-5f);
                outrows[p * 64 + lane]      = dy0 * rs * g0 + be0;
                outrows[p * 64 + 32 + lane] = dy1 * rs * g1 + be1;
                __syncwarp();
            }
            __syncthreads();
            // scatter: 2 tokens per warp per iteration (all 32 lanes active)
            {
                const int half = lane >> 4, q = lane & 15;
                for (int l = w * 2 + half; l < Ldim; l += 16) {
                    int s = (int)tok_as[l] - ac;
                    if ((unsigned)s < (unsigned)an) {
                        float4 v = *(const float4*)&outrows[s * 64 + q * 4];
                        *(float4*)&out[outbase + (size_t)l * 64 + q * 4] = v;
                    }
                }
            }
            __syncthreads();
        }
    }
}

// ---------------------------------------------------------------------------
extern "C" void kernel_launch(void* const* d_in, const int* in_sizes, int n_in,
                              void* d_out, int out_size)
{
    const int*   src = (const int*)d_in[0];
    const int*   dst = (const int*)d_in[1];
    const float* w1  = (const float*)d_in[2];
    const float* b1  = (const float*)d_in[3];
    const float* w2  = (const float*)d_in[4];
    const float* b2  = (const float*)d_in[5];
    const float* Wq  = (const float*)d_in[6];
    const float* Wk  = (const float*)d_in[7];
    const float* Wv  = (const float*)d_in[8];
    const float* Wo  = (const float*)d_in[9];
    const float* bo  = (const float*)d_in[10];
    const float* lng = (const float*)d_in[11];
    const float* lnb = (const float*)d_in[12];
    float* out = (float*)d_out;

    build_tables<<<TMAX, 256>>>(w1, b1, w2, b2, Wq, Wk, Wv);

    cudaFuncSetAttribute(fused_kernel, cudaFuncAttributeMaxDynamicSharedMemorySize, SMEM_BYTES);
    fused_kernel<<<dim3(2, Bdim), 256, SMEM_BYTES>>>(src, dst, Wo, bo, lng, lnb, out);
}

// round 4
// speedup vs baseline: 13.1445x; 1.7768x over previous
#include <cuda_runtime.h>

#define Fdim 64
#define Ldim 512
#define Bdim 256
#define NIDS 2000
#define TMAX 513
#define HSZ  512

// tables: 0=feat(+bo/2), 1=q, 2=k, 3=v@Wo   (token row = T[c0] + T[c1])
__device__ float g_T[4][TMAX * Fdim];

// ---------------------------------------------------------------------------
// One launch builds all 4 tables. Block c: relu -> feat -> {q,k,v} -> v@Wo.
__global__ void build_tables(const float* __restrict__ w1, const float* __restrict__ b1,
                             const float* __restrict__ w2, const float* __restrict__ b2,
                             const float* __restrict__ Wq, const float* __restrict__ Wk,
                             const float* __restrict__ Wv, const float* __restrict__ Wo,
                             const float* __restrict__ bo)
{
    const int c = blockIdx.x, t = threadIdx.x;
    __shared__ float r[Fdim];
    __shared__ float feat[Fdim];
    __shared__ float vrow[Fdim];
    if (t < Fdim) r[t] = fmaxf((float)c * w1[t] + b1[t], 0.f);
    __syncthreads();
    if (t < Fdim) {
        float acc = b2[t];
#pragma unroll 8
        for (int f = 0; f < Fdim; f++) acc += r[f] * w2[f * Fdim + t];
        feat[t] = acc;
        g_T[0][c * Fdim + t] = acc + 0.5f * bo[t];   // bo folded (x2 lookups)
    }
    __syncthreads();
    const int x = t >> 6, g = t & 63;
    if (x >= 1) {
        const float* W = (x == 1) ? Wq : ((x == 2) ? Wk : Wv);
        float acc = 0.f;
#pragma unroll 8
        for (int f = 0; f < Fdim; f++) acc += feat[f] * W[f * Fdim + g];
        if (x == 3) vrow[g] = acc;
        else        g_T[x][c * Fdim + g] = acc;
    }
    __syncthreads();
    if (t < Fdim) {
        float acc = 0.f;
#pragma unroll 8
        for (int e = 0; e < Fdim; e++) acc += vrow[e] * Wo[e * Fdim + t];
        g_T[3][c * Fdim + t] = acc;                  // V@Wo table
    }
}

// ---------------------------------------------------------------------------
// Packed hash entry: (key << 10) | slot.  EMPTY = -1, PENDING slot = 0x3FF.
__device__ __forceinline__ int insert_pair(int key, int* tab, int* counter, int* keys)
{
    unsigned h = ((unsigned)key * 2654435761u) >> 23;   // 9-bit hash
    const int PEND = (key << 10) | 0x3FF;
    while (true) {
        int e = tab[h];
        if (e == -1) e = atomicCAS(&tab[h], -1, PEND);
        if (e == -1) {                    // we claimed this bucket
            int s = atomicAdd(counter, 1);
            keys[s] = key;
            __threadfence_block();
            atomicExch(&tab[h], (key << 10) | s);
            return s;
        }
        if ((e >> 10) == key) {           // wait for owner to publish slot
            int s = e & 0x3FF;
            while (s == 0x3FF) s = ((volatile int*)tab)[h] & 0x3FF;
            return s;
        }
        h = (h + 1) & (HSZ - 1);
    }
}

// Shared plan: hist[2000] (a lo16 | o hi16), hashA[512], hashO[512],
//   a_keys[512], o_keys[512], o_mult[512], counters[8], tok_as ushort[512],
//   ctx2q[4096] (float4-packed ctx@Wo), Ebuf[2048], Vbuf[2048] (alias outrows[4096]),
//   colmax[64], part[256], cvec[128]
#define NINT (2000 + 2 * HSZ + 3 * 512 + 8 + 256)
#define NFLT (4096 + 2048 + 2048 + 64 + 256 + 128)
#define SMEM_BYTES ((NINT + NFLT) * 4)

__global__ void __launch_bounds__(256, 4) fused_kernel(
    const int* __restrict__ src, const int* __restrict__ dst,
    const float* __restrict__ lng, const float* __restrict__ lnb,
    float* __restrict__ out)
{
    extern __shared__ int sm[];
    int* hist     = sm;
    int* hashA    = hist + 2000;
    int* hashO    = hashA + HSZ;
    int* a_keys   = hashO + HSZ;
    int* o_keys   = a_keys + 512;
    int* o_mult   = o_keys + 512;
    int* counters = o_mult + 512;
    unsigned short* tok_as = (unsigned short*)(counters + 8);
    float* ctx2q  = (float*)(counters + 8 + 256);
    float* Ebuf   = ctx2q + 4096;
    float* Vbuf   = Ebuf + 2048;
    float* colmax = Vbuf + 2048;
    float* part   = colmax + 64;
    float* cvec   = part + 256;
    float* outrows = Ebuf;   // 4096, free during Phase C

    const int t = threadIdx.x;
    const int dir = blockIdx.x;
    const int b = blockIdx.y;
    const int* a_ids = (dir == 0 ? src : dst) + b * Ldim;
    const int* o_ids = (dir == 0 ? dst : src) + b * Ldim;

    // ---- init (vectorized) ----
    {
        int4* z = (int4*)hist;           // hist: 2000 ints = 500 int4
        for (int i = t; i < 500; i += 256) z[i] = make_int4(0, 0, 0, 0);
        int4* hneg = (int4*)hashA;       // hashA+hashO: 1024 ints = 256 int4
        for (int i = t; i < 256; i += 256) hneg[i] = make_int4(-1, -1, -1, -1);
        int4* zm = (int4*)o_mult;
        for (int i = t; i < 128; i += 256) zm[i] = make_int4(0, 0, 0, 0);
    }
    if (t < 8) counters[t] = 0;
    if (t < 128) cvec[t] = (t < 64) ? lng[t] : lnb[t - 64];
    __syncthreads();

    // ---- packed histograms: a-count low16, o-count high16 ----
    const int av0 = a_ids[t], av1 = a_ids[t + 256];
    const int ov0 = o_ids[t], ov1 = o_ids[t + 256];
    atomicAdd(&hist[av0], 1);
    atomicAdd(&hist[av1], 1);
    atomicAdd(&hist[ov0], 1 << 16);
    atomicAdd(&hist[ov1], 1 << 16);
    __syncthreads();

    // ---- per-token count pairs -> dedupe ----
#pragma unroll
    for (int rep = 0; rep < 2; rep++) {
        const int l = t + rep * 256;
        const int av = rep ? av1 : av0, ov = rep ? ov1 : ov0;
        int ha = hist[av];
        int akey = av ? (((ha & 0xFFFF) << 10) | (ha >> 16)) : 0;
        tok_as[l] = (unsigned short)insert_pair(akey, hashA, &counters[0], a_keys);
        int ho = hist[ov];
        int okey = ov ? (((ho >> 16) << 10) | (ho & 0xFFFF)) : 0;
        int s = insert_pair(okey, hashO, &counters[1], o_keys);
        atomicAdd(&o_mult[s], 1);
    }
    __syncthreads();
    const int n_ap = counters[0], n_op = counters[1];

    // ---- column max of K over unique o-pairs ----
    const float* Tk = g_T[2];
    {
        const int d = t & 63, grp = t >> 6;
        float m = -3.4e38f;
        for (int p = grp; p < n_op; p += 4) {
            int key = o_keys[p], i0 = key >> 10, i1 = key & 1023;
            m = fmaxf(m, Tk[i0 * 64 + d] + Tk[i1 * 64 + d]);
        }
        part[grp * 64 + d] = m;
    }
    __syncthreads();
    if (t < 64) {
        float m = part[t];
#pragma unroll
        for (int g = 1; g < 4; g++) m = fmaxf(m, part[g * 64 + t]);
        colmax[t] = m;
    }
    __syncthreads();

    // ---- Phase B: ctx2[d][g] = colinv[d] * sum_p E[p][d] * VWo[p][g] ----
    //      colsum accumulated in the same GEMM by ebase==0 threads.
    const float* Tvo = g_T[3];
    {
        const int dbase = (t >> 4) << 2, ebase = (t & 15) << 2;
        float acc[4][4] = {};
        float esum[4] = {};
        for (int pc = 0; pc < n_op; pc += 32) {
            const int cn = min(32, n_op - pc);
            for (int idx = t; idx < cn * 64; idx += 256) {
                int p = idx >> 6, d = idx & 63;
                int key = o_keys[pc + p], i0 = key >> 10, i1 = key & 1023;
                Ebuf[p * 64 + d] = (float)o_mult[pc + p] *
                    __expf(Tk[i0 * 64 + d] + Tk[i1 * 64 + d] - colmax[d]);
            }
            for (int idx = t; idx < cn * 64; idx += 256) {
                int p = idx >> 6, e = idx & 63;
                int key = o_keys[pc + p], i0 = key >> 10, i1 = key & 1023;
                Vbuf[p * 64 + e] = Tvo[i0 * 64 + e] + Tvo[i1 * 64 + e];
            }
            __syncthreads();
            for (int p = 0; p < cn; p++) {
                float4 ev = *(const float4*)&Ebuf[p * 64 + dbase];
                float4 vv = *(const float4*)&Vbuf[p * 64 + ebase];
                float e_[4] = {ev.x, ev.y, ev.z, ev.w};
                float v_[4] = {vv.x, vv.y, vv.z, vv.w};
#pragma unroll
                for (int i = 0; i < 4; i++)
#pragma unroll
                    for (int j = 0; j < 4; j++) acc[i][j] += e_[i] * v_[j];
                if (ebase == 0) {
#pragma unroll
                    for (int i = 0; i < 4; i++) esum[i] += e_[i];
                }
            }
            __syncthreads();
        }
        if (ebase == 0) {
#pragma unroll
            for (int i = 0; i < 4; i++) part[dbase + i] = esum[i];
        }
        __syncthreads();
        // write ctx2 in float4-packed layout:
        //   entry (d*32+lane), d in 0..31, holds:
        //   [0]=(d,lane) [1]=(d,lane+32) [2]=(d+32,lane) [3]=(d+32,lane+32)
        const int dd = dbase & 31, hi = (dbase >> 5) << 1;   // 0 or 2
        const int el = ebase & 31, eh = ebase >> 5;          // 0 or 1
#pragma unroll
        for (int i = 0; i < 4; i++) {
            float inv = 1.0f / part[dbase + i];
#pragma unroll
            for (int j = 0; j < 4; j++)
                ctx2q[((dd + i) * 32 + el + j) * 4 + hi + eh] = acc[i][j] * inv;
        }
    }
    __syncthreads();

    // ---- Phase C: per unique a-pair: q softmax -> attn -> +feat+bo -> LN ----
    const float* Tq = g_T[1];
    const float* Tf = g_T[0];
    {
        const int w = t >> 5, lane = t & 31;
        const float g0 = cvec[lane], g1 = cvec[32 + lane];
        const float be0 = cvec[64 + lane], be1 = cvec[96 + lane];
        const size_t outbase = (((size_t)dir * Bdim + b) * Ldim) * 64;

        for (int ac = 0; ac < n_ap; ac += 64) {
            const int an = min(64, n_ap - ac);
            for (int p = w; p < an; p += 8) {
                int key = a_keys[ac + p], i0 = key >> 10, i1 = key & 1023;
                float q0 = Tq[i0 * 64 + lane] + Tq[i1 * 64 + lane];
                float q1 = Tq[i0 * 64 + 32 + lane] + Tq[i1 * 64 + 32 + lane];
                float f0 = Tf[i0 * 64 + lane] + Tf[i1 * 64 + lane];
                float f1 = Tf[i0 * 64 + 32 + lane] + Tf[i1 * 64 + 32 + lane];
                float m = fmaxf(q0, q1);
#pragma unroll
                for (int off = 16; off; off >>= 1) m = fmaxf(m, __shfl_xor_sync(~0u, m, off));
                float e0 = __expf(q0 - m), e1 = __expf(q1 - m);
                float s = e0 + e1;
#pragma unroll
                for (int off = 16; off; off >>= 1) s += __shfl_xor_sync(~0u, s, off);
                float coef = 0.125f / s;          // F^-0.5 / sum
                float e0c = e0 * coef, e1c = e1 * coef;
                float a0 = 0.f, a1 = 0.f;
#pragma unroll 8
                for (int d = 0; d < 32; d++) {
                    float qlo = __shfl_sync(~0u, e0c, d);
                    float qhi = __shfl_sync(~0u, e1c, d);
                    float4 cp = *(const float4*)&ctx2q[(d * 32 + lane) * 4];
                    a0 += qlo * cp.x + qhi * cp.z;
                    a1 += qlo * cp.y + qhi * cp.w;
                }
                float y0 = f0 + a0;               // bo already folded into Tf
                float y1 = f1 + a1;
                float mu = y0 + y1;
#pragma unroll
                for (int off = 16; off; off >>= 1) mu += __shfl_xor_sync(~0u, mu, off);
                mu *= (1.0f / 64.0f);
                float dy0 = y0 - mu, dy1 = y1 - mu;
                float var = dy0 * dy0 + dy1 * dy1;
#pragma unroll
                for (int off = 16; off; off >>= 1) var += __shfl_xor_sync(~0u, var, off);
                var *= (1.0f / 64.0f);
                float rs = rsqrtf(var + 1e-5f);
                outrows[p * 64 + lane]      = dy0 * rs * g0 + be0;
                outrows[p * 64 + 32 + lane] = dy1 * rs * g1 + be1;
            }
            __syncthreads();
            // scatter: 2 tokens per warp per iteration
            {
                const int half = lane >> 4, q = lane & 15;
                for (int l = w * 2 + half; l < Ldim; l += 16) {
                    int s = (int)tok_as[l] - ac;
                    if ((unsigned)s < (unsigned)an) {
                        float4 v = *(const float4*)&outrows[s * 64 + q * 4];
                        *(float4*)&out[outbase + (size_t)l * 64 + q * 4] = v;
                    }
                }
            }
            __syncthreads();
        }
    }
}

// ---------------------------------------------------------------------------
extern "C" void kernel_launch(void* const* d_in, const int* in_sizes, int n_in,
                              void* d_out, int out_size)
{
    const int*   src = (const int*)d_in[0];
    const int*   dst = (const int*)d_in[1];
    const float* w1  = (const float*)d_in[2];
    const float* b1  = (const float*)d_in[3];
    const float* w2  = (const float*)d_in[4];
    const float* b2  = (const float*)d_in[5];
    const float* Wq  = (const float*)d_in[6];
    const float* Wk  = (const float*)d_in[7];
    const float* Wv  = (const float*)d_in[8];
    const float* Wo  = (const float*)d_in[9];
    const float* bo  = (const float*)d_in[10];
    const float* lng = (const float*)d_in[11];
    const float* lnb = (const float*)d_in[12];
    float* out = (float*)d_out;

    build_tables<<<TMAX, 256>>>(w1, b1, w2, b2, Wq, Wk, Wv, Wo, bo);

    cudaFuncSetAttribute(fused_kernel, cudaFuncAttributeMaxDynamicSharedMemorySize, SMEM_BYTES);
    fused_kernel<<<dim3(2, Bdim), 256, SMEM_BYTES>>>(src, dst, lng, lnb, out);
}